// round 16
// baseline (speedup 1.0000x reference)
#include <cuda_runtime.h>
#include <cuda_fp16.h>
#include <math.h>
#include <stdint.h>

// ---------------- problem constants ----------------
#define NB   64
#define LT   1024
#define KK   64
#define DD   300
#define HH   5
#define ET   2048
#define EI   512

#define KP   1536
#define NP   320
#define BK   32
#define NCHUNK (KP/BK)
#define WTSZ ((size_t)2*320*KP)

// ---------------- scratch ----------------
__device__ __half g_ah  [(size_t)NB*LT*KP];
__device__ __half g_ahi [(size_t)NB*KK*KP];
__device__ float  g_C   [(size_t)NB*LT*NP];
__device__ float  g_Ci  [(size_t)NB*KK*NP];
__device__ __half g_wtx [2*WTSZ];
__device__ __half g_wti [2*WTSZ];
__device__ float  g_Sx  [2*10*DD];
__device__ float  g_Si  [2*10*DD];
__device__ float  g_y   [(size_t)NB*LT*DD];
__device__ float  g_x   [(size_t)NB*(LT+1)*DD];
__device__ float  g_v3a [(size_t)NB*KK*DD];
__device__ float  g_v3b [(size_t)NB*KK*DD];
__device__ float  g_asrc [NB*LT*HH];
__device__ float  g_adst [NB*LT*HH];
__device__ float  g_asrci[NB*KK*HH];
__device__ float  g_adsti[NB*KK*HH];
__device__ float  g_al_ [NB*ET*HH];
__device__ float  g_ali [NB*EI*HH];
__device__ int    g_offt[NB*(LT+1)];
__device__ int    g_eidt[NB*ET];
__device__ int    g_offi[KK+1];
__device__ int    g_eidi[EI];
__device__ float  g_sbuf[NB*(LT+1)];
__device__ float  g_prob[NB*(LT+1)];
__device__ float  g_part[NB*16*DD];
__device__ float  g_partc[NB*16*DD];

__device__ __forceinline__ float wredsum(float v){
    #pragma unroll
    for (int o=16;o;o>>=1) v += __shfl_down_sync(0xffffffffu, v, o);
    return v;
}
__device__ __forceinline__ void mma_f16(float* c, uint32_t a0,uint32_t a1,uint32_t a2,uint32_t a3,
                                        uint32_t b0, uint32_t b1){
    asm volatile("mma.sync.aligned.m16n8k16.row.col.f32.f16.f16.f32 "
                 "{%0,%1,%2,%3},{%4,%5,%6,%7},{%8,%9},{%0,%1,%2,%3};"
                 : "+f"(c[0]),"+f"(c[1]),"+f"(c[2]),"+f"(c[3])
                 : "r"(a0),"r"(a1),"r"(a2),"r"(a3),"r"(b0),"r"(b1));
}
__device__ __forceinline__ void ldmx4(uint32_t addr, uint32_t* r){
    asm volatile("ldmatrix.sync.aligned.m8n8.x4.shared.b16 {%0,%1,%2,%3}, [%4];"
                 : "=r"(r[0]),"=r"(r[1]),"=r"(r[2]),"=r"(r[3]) : "r"(addr));
}
__device__ __forceinline__ void ldmx2(uint32_t addr, uint32_t* r){
    asm volatile("ldmatrix.sync.aligned.m8n8.x2.shared.b16 {%0,%1}, [%2];"
                 : "=r"(r[0]),"=r"(r[1]) : "r"(addr));
}
#define CP16(sm, gp) asm volatile("cp.async.cg.shared.global [%0], [%1], 16;" :: "r"(sm), "l"(gp))
#define CP_COMMIT()  asm volatile("cp.async.commit_group;")

// ================== device bodies ==================

__device__ void d_csr(const int* EIp, long eiStride, int nodes, int E,
                      int* off, int* eid, int perBatch, int n, int* cnt, int* cur)
{
    for (int i=threadIdx.x; i<=nodes; i+=blockDim.x) cnt[i]=0;
    __syncthreads();
    const int* dstp = EIp + (size_t)eiStride*n + E;
    for (int j=threadIdx.x; j<E; j+=blockDim.x) atomicAdd(&cnt[dstp[j]+1], 1);
    __syncthreads();
    if (threadIdx.x==0){
        int run=0;
        for (int i=0;i<=nodes;i++){ run += cnt[i]; cnt[i]=run; }
    }
    __syncthreads();
    int* offg = off + (perBatch ? n*(nodes+1) : 0);
    for (int i=threadIdx.x; i<=nodes; i+=blockDim.x) offg[i]=cnt[i];
    for (int i=threadIdx.x; i<nodes;  i+=blockDim.x) cur[i]=cnt[i];
    __syncthreads();
    int* eidg = eid + (perBatch ? n*E : 0);
    for (int j=threadIdx.x; j<E; j+=blockDim.x){
        int d = dstp[j];
        int pos = atomicAdd(&cur[d], 1);
        eidg[pos] = j;
    }
}

__device__ void d_scores(const float* __restrict__ X, const float* __restrict__ S,
                         int row, int rows, float* asrc, float* adst, int lane)
{
    if (row >= rows) return;
    const float* xr = X + (size_t)row*DD;
    float acc[10];
    #pragma unroll
    for (int j=0;j<10;j++) acc[j]=0.f;
    for (int d=lane; d<DD; d+=32){
        float xv = xr[d];
        #pragma unroll
        for (int j=0;j<10;j++) acc[j] += xv * S[j*DD+d];
    }
    #pragma unroll
    for (int j=0;j<10;j++) acc[j] = wredsum(acc[j]);
    if (lane==0){
        #pragma unroll
        for (int h=0;h<HH;h++){ asrc[row*HH+h]=acc[h]; adst[row*HH+h]=acc[HH+h]; }
    }
}

__device__ void d_logits(const float* __restrict__ X, int rows,
                         const float* __restrict__ w, const float* __restrict__ b,
                         const int* __restrict__ mask, float* s, int row, int lane)
{
    if (row >= rows) return;
    const float* xr = X + (size_t)row*DD;
    float acc=0.f;
    for (int d=lane; d<DD; d+=32) acc += xr[d]*w[d];
    acc = wredsum(acc);
    if (lane==0) s[row] = mask[row] ? -1e30f : acc + b[0];
}

__device__ void d_alpha(const int* off, const int* eid, int perBatch,
                        const int* EIp, long eiStride,
                        const float* asrc, const float* adst,
                        float* alpha, int nodes, int E, int total, int idx)
{
    if (idx >= total) return;
    int h = idx % HH;
    int node = (idx/HH) % nodes;
    int n = idx/(HH*nodes);
    const int* o  = off + (perBatch ? n*(nodes+1) : 0);
    const int* ee = eid + (perBatch ? n*E : 0);
    int s=o[node], t=o[node+1];
    if (s==t) return;
    const int* srcp = EIp + (size_t)eiStride*n;
    const float* as_ = asrc + (size_t)n*nodes*HH;
    float ad = adst[((size_t)n*nodes+node)*HH + h];
    float m=-1e30f;
    for (int q=s;q<t;q++){
        float e = as_[srcp[ee[q]]*HH + h] + ad;
        e = e > 0.f ? e : 0.2f*e;
        m = fmaxf(m, e);
    }
    float den=0.f;
    for (int q=s;q<t;q++){
        float e = as_[srcp[ee[q]]*HH + h] + ad;
        e = e > 0.f ? e : 0.2f*e;
        den += expf(e-m);
    }
    float inv = 1.f/(den + 1e-16f);
    for (int q=s;q<t;q++){
        int j = ee[q];
        float e = as_[srcp[j]*HH + h] + ad;
        e = e > 0.f ? e : 0.2f*e;
        alpha[((size_t)n*E + j)*HH + h] = expf(e-m)*inv;
    }
}

// softmax over Lrow with 256 threads
__device__ void d_softmax256(const float* __restrict__ s, int Lrow, float* __restrict__ p,
                             int n, float* red)
{
    int tid = threadIdx.x, warp=tid>>5, lane=tid&31;
    const float* sb = s + (size_t)n*Lrow;
    float m=-1e30f;
    for (int l=tid; l<Lrow; l+=256) m = fmaxf(m, sb[l]);
    #pragma unroll
    for (int o=16;o;o>>=1) m = fmaxf(m, __shfl_down_sync(0xffffffffu, m, o));
    if (lane==0) red[warp]=m;
    __syncthreads();
    if (tid==0){ float v=red[0]; for(int i=1;i<8;i++) v=fmaxf(v,red[i]); red[0]=v; }
    __syncthreads();
    m = red[0];
    __syncthreads();
    float sum=0.f;
    for (int l=tid; l<Lrow; l+=256) sum += expf(sb[l]-m);
    sum = wredsum(sum);
    if (lane==0) red[warp]=sum;
    __syncthreads();
    if (tid==0){ float v=0.f; for(int i=0;i<8;i++) v+=red[i]; red[0]=v; }
    __syncthreads();
    float inv = 1.f/red[0];
    for (int l=tid; l<Lrow; l+=256) p[(size_t)n*Lrow + l] = expf(sb[l]-m)*inv;
}

// xagg: 320 threads, 1 col/thread
__device__ void d_xagg320(const float* __restrict__ X, const float* __restrict__ alpha,
                          const int* off, const int* eid, int perBatch,
                          const int* EIp, long eiStride, int nodes, int E,
                          __half* outA, int n, int node)
{
    int tid = threadIdx.x;
    const int* o  = off + (perBatch ? n*(nodes+1) : 0);
    const int* ee = eid + (perBatch ? n*E : 0);
    int s=o[node], t=o[node+1];
    const int* srcp = EIp + (size_t)eiStride*n;
    const float* Xb = X + (size_t)n*nodes*DD;
    const float* al0 = alpha + (size_t)n*E*HH;
    __half* oh = outA + (size_t)(n*nodes+node)*KP;

    if (tid < DD){
        float acc[HH] = {0,0,0,0,0};
        for (int q=s; q<t; q++){
            int j = ee[q];
            float x = Xb[(size_t)srcp[j]*DD + tid];
            const float* ap = al0 + (size_t)j*HH;
            #pragma unroll
            for (int h=0;h<HH;h++) acc[h] += ap[h]*x;
        }
        #pragma unroll
        for (int h=0;h<HH;h++) oh[h*DD + tid] = __float2half_rn(acc[h]);
    }
    if (tid < KP - HH*DD)
        oh[HH*DD + tid] = __float2half_rn(0.f);
}

// a1 weighted-sum + c partials (320 threads)
__device__ void d_wsumc(const float* __restrict__ t2, const float* __restrict__ score,
                        const float* __restrict__ p,
                        float* partW, float* partC, int n, int cid)
{
    int d = threadIdx.x;
    if (d >= DD) return;
    int chunk = LT/16;
    int l0 = cid*chunk, l1 = l0+chunk;
    const float* Tb = t2    + (size_t)n*LT*DD;
    const float* Sb = score + (size_t)n*LT*DD;
    const float* pb = p + (size_t)n*LT;
    float aw=0.f, ac=0.f;
    for (int l=l0; l<l1; l++){
        float tv = Tb[(size_t)l*DD+d];
        aw += pb[l]*tv;
        ac += Sb[(size_t)l*DD+d]*tv;
    }
    partW[((size_t)n*16+cid)*DD + d] = aw;
    partC[((size_t)n*16+cid)*DD + d] = ac;
}

// post (+optional fused next-layer scores); 128 threads; sh = 64-float scratch
__device__ void d_post(const float* __restrict__ C, const float* __restrict__ bias,
                       const int* __restrict__ gnnMask,
                       const float* __restrict__ lng, const float* __restrict__ lnb,
                       float* out, long outBatchStride, int nodes,
                       const float* __restrict__ Snext, float* asrc, float* adst,
                       int n, int node, float* sh)
{
    int tid = threadIdx.x;
    size_t row = (size_t)n*nodes + node;
    const float* cr = C + row*NP;
    int d0=tid, d1=tid+128, d2=tid+256;
    bool v2 = (d2 < DD);
    bool msk = (gnnMask != nullptr) && (gnnMask[n] != 0);
    float g0 = msk ? 0.f : cr[d0] + bias[d0];
    float g1 = msk ? 0.f : cr[d1] + bias[d1];
    float g2 = v2 ? (msk ? 0.f : cr[d2] + bias[d2]) : 0.f;
    float r0 = fmaxf(g0,0.f), r1 = fmaxf(g1,0.f), r2 = fmaxf(g2,0.f);

    float* sS = sh;       // [4]
    float* sQ = sh + 4;   // [4]
    float* sJ = sh + 8;   // [4][10]
    int warp = tid>>5, lane = tid&31;
    float lsum = r0 + r1 + r2;
    float lsq  = r0*r0 + r1*r1 + r2*r2;
    lsum = wredsum(lsum); lsq = wredsum(lsq);
    if (lane==0){ sS[warp]=lsum; sQ[warp]=lsq; }
    __syncthreads();
    if (tid==0){
        float S=0.f, Q=0.f;
        for (int w=0;w<4;w++){ S+=sS[w]; Q+=sQ[w]; }
        sS[0]=S; sQ[0]=Q;
    }
    __syncthreads();
    float mu  = sS[0]*(1.f/300.f);
    float var = sQ[0]*(1.f/300.f) - mu*mu;
    float rstd = rsqrtf(var + 1e-5f);
    float o0 = (r0-mu)*rstd*lng[d0] + lnb[d0];
    float o1 = (r1-mu)*rstd*lng[d1] + lnb[d1];
    float o2 = v2 ? ((r2-mu)*rstd*lng[d2] + lnb[d2]) : 0.f;
    float* orow = out + (size_t)n*outBatchStride + (size_t)node*DD;
    orow[d0] = o0;
    orow[d1] = o1;
    if (v2) orow[d2] = o2;

    if (Snext){
        #pragma unroll
        for (int j=0;j<10;j++){
            const float* sv = Snext + j*DD;
            float p = o0*sv[d0] + o1*sv[d1] + (v2 ? o2*sv[d2] : 0.f);
            p = wredsum(p);
            if (lane==0) sJ[warp*10+j] = p;
        }
        __syncthreads();
        if (tid < 10){
            float v = sJ[tid] + sJ[10+tid] + sJ[20+tid] + sJ[30+tid];
            if (tid < HH) asrc[row*HH + tid] = v;
            else          adst[row*HH + (tid-HH)] = v;
        }
    }
}

// part-reduce + dot with 128 threads; tb = DD floats shared
__device__ void d_dotred128(const float* __restrict__ part, const float* __restrict__ V,
                            float* out, int colOff, int n, float* tb)
{
    int tid = threadIdx.x;
    for (int d=tid; d<DD; d+=128){
        float acc=0.f;
        #pragma unroll
        for (int c=0;c<16;c++) acc += part[((size_t)n*16+c)*DD + d];
        tb[d] = acc;
    }
    __syncthreads();
    int warp = tid>>5, lane = tid&31;
    for (int k=warp; k<KK; k+=4){
        const float* v = V + ((size_t)n*KK + k)*DD;
        float acc=0.f;
        for (int d=lane; d<DD; d+=32) acc += tb[d]*v[d];
        acc = wredsum(acc);
        if (lane==0) out[n*128 + colOff + k] = acc * 0.05773502691896258f;
    }
}

__device__ void d_cred128(const float* __restrict__ part, float* xbuf, int n)
{
    for (int d=threadIdx.x; d<DD; d+=128){
        float acc=0.f;
        #pragma unroll
        for (int c=0;c<16;c++) acc += part[((size_t)n*16+c)*DD + d];
        xbuf[((size_t)n*(LT+1) + LT)*DD + d] = acc;
    }
}

// ================== kernels ==================

__global__ void k_csr2(const int* __restrict__ eiT, const int* __restrict__ eiI,
                       int* offT, int* eidT, int* offI, int* eidI)
{
    __shared__ int cnt[LT+1];
    __shared__ int cur[LT];
    if (blockIdx.x < NB)
        d_csr(eiT, 2L*ET, LT, ET, offT, eidT, 1, blockIdx.x, cnt, cur);
    else
        d_csr(eiI, 0L, KK, EI, offI, eidI, 0, 0, cnt, cur);
}

__global__ void k_mkS4(const float* __restrict__ txtW, const float* __restrict__ txtAS,
                       const float* __restrict__ txtAD,
                       const float* __restrict__ imgW, const float* __restrict__ imgAS,
                       const float* __restrict__ imgAD,
                       float* __restrict__ Sx, float* __restrict__ Si)
{
    int slot = blockIdx.y;
    int layer = slot & 1, isImg = slot >> 1;
    const float* W   = (isImg ? imgW  : txtW)  + (size_t)layer*DD*HH*DD;
    const float* aS  = (isImg ? imgAS : txtAS) + layer*HH*DD;
    const float* aD  = (isImg ? imgAD : txtAD) + layer*HH*DD;
    float* S         = (isImg ? Si    : Sx)    + layer*10*DD;

    int warp = threadIdx.x>>5, lane = threadIdx.x&31;
    int q = blockIdx.x*8 + warp;
    if (q >= 10*DD) return;
    int j = q/DD, d = q%DD;
    int h = j%HH;
    const float* att = (j<HH ? aS : aD) + h*DD;
    const float* wrow = W + ((size_t)d*HH + h)*DD;
    float acc=0.f;
    for (int dd=lane; dd<DD; dd+=32) acc += wrow[dd]*att[dd];
    acc = wredsum(acc);
    if (lane==0) S[q] = acc;
}

__global__ void k_mkWt4(const float* __restrict__ txtW, const float* __restrict__ imgW,
                        __half* __restrict__ wtx, __half* __restrict__ wti)
{
    int slot = blockIdx.y;
    int layer = slot & 1, isImg = slot >> 1;
    const float* W = (isImg ? imgW : txtW) + (size_t)layer*DD*HH*DD;
    __half* wt     = (isImg ? wti  : wtx)  + (size_t)layer*WTSZ;

    int idx = blockIdx.x*blockDim.x + threadIdx.x;
    if (idx >= 320*KP) return;
    int n = idx / KP, k = idx % KP;
    float v = 0.f;
    if (n < DD && k < HH*DD){
        int h = k/DD, d = k%DD;
        v = W[((size_t)d*HH + h)*DD + n] * 0.2f;
    }
    __half hi = __float2half_rn(v);
    float lo = v - __half2float(hi);
    wt[idx] = hi;
    wt[(size_t)320*KP + idx] = __float2half_rn(lo);
}

// scores(txt) + scores(img) + logits(a1); 256 threads
#define MS_T  ((NB*LT)/8)
#define MS_I  ((NB*KK)/8)
__global__ void k_ms0(const float* __restrict__ t2, const float* __restrict__ v2,
                      const float* __restrict__ Sx, const float* __restrict__ Si,
                      const float* __restrict__ w1, const float* __restrict__ b1,
                      const int* __restrict__ kpm,
                      float* asT, float* adT, float* asI, float* adI, float* sbuf)
{
    int bx = blockIdx.x;
    int warp = threadIdx.x>>5, lane = threadIdx.x&31;
    if (bx < MS_T){
        d_scores(t2, Sx, bx*8+warp, NB*LT, asT, adT, lane);
    } else if (bx < MS_T + MS_I){
        d_scores(v2, Si, (bx-MS_T)*8+warp, NB*KK, asI, adI, lane);
    } else {
        d_logits(t2, NB*LT, w1, b1, kpm, sbuf, (bx-MS_T-MS_I)*8+warp, lane);
    }
}

// alpha(txt) + alpha(img) + [softmax(a1)]; 256 threads
#define AL_T  ((NB*LT*HH+255)/256)
#define AL_I  ((NB*KK*HH+255)/256)
__global__ void k_malpha(const int* offT, const int* eidT, const int* __restrict__ eiT,
                         const float* asT, const float* adT, float* alT,
                         const int* offI, const int* eidI, const int* __restrict__ eiI,
                         const float* asI, const float* adI, float* alI,
                         const float* sbuf, float* prob)
{
    __shared__ float red[8];
    int bx = blockIdx.x;
    if (bx < AL_T){
        d_alpha(offT, eidT, 1, eiT, 2L*ET, asT, adT, alT, LT, ET, NB*LT*HH,
                bx*256 + threadIdx.x);
    } else if (bx < AL_T + AL_I){
        d_alpha(offI, eidI, 0, eiI, 0L, asI, adI, alI, KK, EI, NB*KK*HH,
                (bx-AL_T)*256 + threadIdx.x);
    } else {
        d_softmax256(sbuf, LT, prob, bx - AL_T - AL_I, red);
    }
}

// xagg(txt) + xagg(img) + [wsumc]; 320 threads
#define XG_T (NB*LT)
#define XG_I (NB*KK)
__global__ void k_mxagg(const float* __restrict__ Xt, const float* al_t,
                        const int* offT, const int* eidT, const int* __restrict__ eiT,
                        __half* ahT,
                        const float* __restrict__ Xi, const float* al_i,
                        const int* offI, const int* eidI, const int* __restrict__ eiI,
                        __half* ahI,
                        const float* __restrict__ t2, const float* __restrict__ score,
                        const float* __restrict__ prob, float* partW, float* partC)
{
    int bx = blockIdx.x;
    if (bx < XG_T){
        d_xagg320(Xt, al_t, offT, eidT, 1, eiT, 2L*ET, LT, ET, ahT, bx/LT, bx%LT);
    } else if (bx < XG_T + XG_I){
        int r = bx - XG_T;
        d_xagg320(Xi, al_i, offI, eidI, 0, eiI, 0L, KK, EI, ahI, r/KK, r%KK);
    } else {
        int r = bx - XG_T - XG_I;
        d_wsumc(t2, score, prob, partW, partC, r>>4, r&15);
    }
}

// merged txt+img GEMM; 512 threads
#define APL 10240
#define BPL 12800
#define STG (APL + 2*BPL)
#define GSMEM (3*STG)
__global__ void __launch_bounds__(512,1)
k_mgemm(const __half* __restrict__ At, const __half* __restrict__ wtT, float* __restrict__ Ct,
        const __half* __restrict__ Ai, const __half* __restrict__ wtI, float* __restrict__ Ci)
{
    extern __shared__ char smem[];
    uint32_t sm_u = (uint32_t)__cvta_generic_to_shared(smem);

    const __half* Ain; const __half* wt; float* C; int bm;
    int by = blockIdx.y;
    if (by < (NB*LT)/128){ Ain = At; wt = wtT; C = Ct; bm = by*128; }
    else                 { Ain = Ai; wt = wtI; C = Ci; bm = (by-(NB*LT)/128)*128; }

    int tid = threadIdx.x;
    int bn = blockIdx.x*160;
    int warp = tid>>5, lane = tid&31;
    int wm = warp>>2, wn = warp&3;
    int g = lane>>2, tig = lane&3;

    float acc[2][5][4];
    #pragma unroll
    for (int t=0;t<2;t++)
        #pragma unroll
        for (int j=0;j<5;j++)
            #pragma unroll
            for (int r=0;r<4;r++) acc[t][j][r]=0.f;

    uint32_t a_frag  = (uint32_t)((wm*32 + (lane&7) + ((lane>>3)&1)*8)*80 + ((lane>>4)&1)*16);
    uint32_t b_frag  = (uint32_t)(((lane&7) + ((lane>>4)&1)*8)*80 + ((lane>>3)&1)*16);
    uint32_t b_frag2 = (uint32_t)(((wn*40+32) + (lane&7))*80 + ((lane>>3)&1)*16);

    int ar = tid>>2, as_ = tid&3;
    const __half* gAh = Ain + (size_t)(bm+ar)*KP + as_*8;
    uint32_t aoff = (uint32_t)(ar*80 + as_*16);
    const __half* WTh = wt;
    const __half* WTl = wt + (size_t)320*KP;
    int b0n = tid>>2,       b0s = tid&3;
    int b1n = (tid+512)>>2, b1s = tid&3;
    bool bv = (tid < 128);
    const __half* gB0h = WTh + (size_t)(bn+b0n)*KP + b0s*8;
    const __half* gB0l = WTl + (size_t)(bn+b0n)*KP + b0s*8;
    const __half* gB1h = WTh + (size_t)(bn+b1n)*KP + b1s*8;
    const __half* gB1l = WTl + (size_t)(bn+b1n)*KP + b1s*8;
    uint32_t bo0 = (uint32_t)(b0n*80 + b0s*16);
    uint32_t bo1 = (uint32_t)(b1n*80 + b1s*16);

    #define COPY_CHUNK(kc, s) do { \
        int _k = (kc)*BK; \
        uint32_t _b = sm_u + (s)*STG; \
        CP16(_b + aoff, gAh + _k); \
        CP16(_b + APL + bo0, gB0h + _k); \
        CP16(_b + APL + BPL + bo0, gB0l + _k); \
        if (bv){ \
            CP16(_b + APL + bo1, gB1h + _k); \
            CP16(_b + APL + BPL + bo1, gB1l + _k); \
        } \
        CP_COMMIT(); \
    } while(0)

    COPY_CHUNK(0, 0);
    COPY_CHUNK(1, 1);
    int s = 0;
    for (int kc=0; kc<NCHUNK; kc++){
        if (kc+2 < NCHUNK){
            COPY_CHUNK(kc+2, (kc+2)%3);
            asm volatile("cp.async.wait_group 2;");
        } else if (kc+1 < NCHUNK){
            asm volatile("cp.async.wait_group 1;");
        } else {
            asm volatile("cp.async.wait_group 0;");
        }
        __syncthreads();
        uint32_t Ab = sm_u + s*STG;
        uint32_t Bh = Ab + APL;
        uint32_t Bl = Bh + BPL;
        #pragma unroll
        for (int ks=0; ks<2; ks++){
            uint32_t kbyte = ks*32;
            uint32_t ahf[2][4];
            #pragma unroll
            for (int t=0;t<2;t++)
                ldmx4(Ab + t*(16*80) + kbyte + a_frag, ahf[t]);
            uint32_t bh[5][2], bl[5][2];
            #pragma unroll
            for (int jj=0;jj<2;jj++){
                uint32_t r4[4];
                uint32_t base = (uint32_t)((wn*40 + jj*16)*80) + kbyte + b_frag;
                ldmx4(Bh + base, r4);
                bh[jj*2+0][0]=r4[0]; bh[jj*2+0][1]=r4[1];
                bh[jj*2+1][0]=r4[2]; bh[jj*2+1][1]=r4[3];
                ldmx4(Bl + base, r4);
                bl[jj*2+0][0]=r4[0]; bl[jj*2+0][1]=r4[1];
                bl[jj*2+1][0]=r4[2]; bl[jj*2+1][1]=r4[3];
            }
            {
                uint32_t r2[2];
                ldmx2(Bh + kbyte + b_frag2, r2);
                bh[4][0]=r2[0]; bh[4][1]=r2[1];
                ldmx2(Bl + kbyte + b_frag2, r2);
                bl[4][0]=r2[0]; bl[4][1]=r2[1];
            }
            #pragma unroll
            for (int j=0;j<5;j++){
                #pragma unroll
                for (int t=0;t<2;t++){
                    mma_f16(acc[t][j], ahf[t][0],ahf[t][1],ahf[t][2],ahf[t][3], bh[j][0],bh[j][1]);
                    mma_f16(acc[t][j], ahf[t][0],ahf[t][1],ahf[t][2],ahf[t][3], bl[j][0],bl[j][1]);
                }
            }
        }
        __syncthreads();
        s = (s+1)%3;
    }

    #pragma unroll
    for (int t=0;t<2;t++){
        int row0 = bm + wm*32 + t*16 + g;
        #pragma unroll
        for (int j=0;j<5;j++){
            int n0 = bn + wn*40 + j*8 + 2*tig;
            *(float2*)&C[(size_t)row0*NP + n0]     = make_float2(acc[t][j][0], acc[t][j][1]);
            *(float2*)&C[(size_t)(row0+8)*NP + n0] = make_float2(acc[t][j][2], acc[t][j][3]);
        }
    }
}

// post(txt)+post(img)+[dotred+c_red]; 128 threads
__global__ void k_mpost(const float* Ct, const float* biasT, const int* gnn,
                        const float* lng, const float* lnb,
                        float* outT, long strideT,
                        const float* Ci, const float* biasI, float* outI,
                        const float* SnT, float* asT, float* adT,
                        const float* SnI, float* asI, float* adI,
                        const float* partW, const float* partC,
                        const float* v2, float* dout, float* xbuf)
{
    __shared__ float sh[DD];
    int bx = blockIdx.x;
    if (bx < XG_T){
        d_post(Ct, biasT, gnn, lng, lnb, outT, strideT, LT, SnT, asT, adT,
               bx/LT, bx%LT, sh);
    } else if (bx < XG_T + XG_I){
        int r = bx - XG_T;
        d_post(Ci, biasI, nullptr, lng, lnb, outI, (long)KK*DD, KK, SnI, asI, adI,
               r/KK, r%KK, sh);
    } else if (bx < XG_T + XG_I + NB){
        d_dotred128(partW, v2, dout, 0, bx - XG_T - XG_I, sh);
    } else {
        d_cred128(partC, xbuf, bx - XG_T - XG_I - NB);
    }
}

// ---- a2 standalone kernels ----
__global__ void k_logits(const float* __restrict__ X, int rows,
                         const float* __restrict__ w, const float* __restrict__ b,
                         const int* __restrict__ mask, float* __restrict__ s)
{
    int warp = threadIdx.x>>5, lane = threadIdx.x&31;
    d_logits(X, rows, w, b, mask, s, blockIdx.x*8+warp, lane);
}

__global__ void k_softmax(const float* __restrict__ s, int Lrow, float* __restrict__ p)
{
    __shared__ float red[8];
    d_softmax256(s, Lrow, p, blockIdx.x, red);
}

__global__ void k_wsum_part(const float* __restrict__ X, int Lrow,
                            const float* __restrict__ p, float* __restrict__ part)
{
    int n = blockIdx.x, cid = blockIdx.y;
    int d = threadIdx.x;
    if (d >= DD) return;
    int chunk = (Lrow+15)/16;
    int l0 = cid*chunk, l1 = min(Lrow, l0+chunk);
    const float* Xb = X + ((size_t)n*Lrow)*DD;
    const float* pb = p + (size_t)n*Lrow;
    float acc=0.f;
    for (int l=l0; l<l1; l++) acc += pb[l]*Xb[(size_t)l*DD+d];
    part[((size_t)n*16+cid)*DD + d] = acc;
}

__global__ void k_dotred(const float* __restrict__ part, const float* __restrict__ V,
                         float* __restrict__ out, int colOff)
{
    __shared__ float tb[DD];
    d_dotred128(part, V, out, colOff, blockIdx.x, tb);
}

// ---------------- launch ----------------
extern "C" void kernel_launch(void* const* d_in, const int* in_sizes, int n_in,
                              void* d_out, int out_size)
{
    const float* t2    = (const float*)d_in[0];
    const float* v2    = (const float*)d_in[1];
    const float* score = (const float*)d_in[2];
    const int*   ei_t  = (const int*)  d_in[3];
    const int*   gnn   = (const int*)  d_in[4];
    const int*   kpm   = (const int*)  d_in[5];
    const int*   npm   = (const int*)  d_in[6];
    const int*   ei_i  = (const int*)  d_in[7];
    const float* txtW  = (const float*)d_in[8];
    const float* txtAS = (const float*)d_in[9];
    const float* txtAD = (const float*)d_in[10];
    const float* txtB  = (const float*)d_in[11];
    const float* imgW  = (const float*)d_in[12];
    const float* imgAS = (const float*)d_in[13];
    const float* imgAD = (const float*)d_in[14];
    const float* imgB  = (const float*)d_in[15];
    const float* w1    = (const float*)d_in[16];
    const float* b1    = (const float*)d_in[17];
    const float* w2    = (const float*)d_in[18];
    const float* b2    = (const float*)d_in[19];
    const float* lng   = (const float*)d_in[20];
    const float* lnb   = (const float*)d_in[21];
    float* out = (float*)d_out;

    __half *p_ah,*p_ahi,*p_wtx,*p_wti;
    float *p_C,*p_Ci,*p_Sx,*p_Si,*p_y,*p_x,*p_v3a,*p_v3b;
    float *p_asrc,*p_adst,*p_asrci,*p_adsti,*p_al,*p_ali;
    float *p_sbuf,*p_prob,*p_part,*p_partc;
    int *p_offt,*p_eidt,*p_offi,*p_eidi;
    cudaGetSymbolAddress((void**)&p_ah, g_ah);
    cudaGetSymbolAddress((void**)&p_ahi, g_ahi);
    cudaGetSymbolAddress((void**)&p_C, g_C);
    cudaGetSymbolAddress((void**)&p_Ci, g_Ci);
    cudaGetSymbolAddress((void**)&p_wtx, g_wtx);
    cudaGetSymbolAddress((void**)&p_wti, g_wti);
    cudaGetSymbolAddress((void**)&p_Sx, g_Sx);
    cudaGetSymbolAddress((void**)&p_Si, g_Si);
    cudaGetSymbolAddress((void**)&p_y, g_y);
    cudaGetSymbolAddress((void**)&p_x, g_x);
    cudaGetSymbolAddress((void**)&p_v3a, g_v3a);
    cudaGetSymbolAddress((void**)&p_v3b, g_v3b);
    cudaGetSymbolAddress((void**)&p_asrc, g_asrc);
    cudaGetSymbolAddress((void**)&p_adst, g_adst);
    cudaGetSymbolAddress((void**)&p_asrci, g_asrci);
    cudaGetSymbolAddress((void**)&p_adsti, g_adsti);
    cudaGetSymbolAddress((void**)&p_al, g_al_);
    cudaGetSymbolAddress((void**)&p_ali, g_ali);
    cudaGetSymbolAddress((void**)&p_sbuf, g_sbuf);
    cudaGetSymbolAddress((void**)&p_prob, g_prob);
    cudaGetSymbolAddress((void**)&p_part, g_part);
    cudaGetSymbolAddress((void**)&p_partc, g_partc);
    cudaGetSymbolAddress((void**)&p_offt, g_offt);
    cudaGetSymbolAddress((void**)&p_eidt, g_eidt);
    cudaGetSymbolAddress((void**)&p_offi, g_offi);
    cudaGetSymbolAddress((void**)&p_eidi, g_eidi);

    static bool inited = false;
    if (!inited){
        cudaFuncSetAttribute(k_mgemm, cudaFuncAttributeMaxDynamicSharedMemorySize, GSMEM);
        inited = true;
    }

    // prep
    k_mkS4 <<<dim3((10*DD+7)/8, 4), 256>>>(txtW, txtAS, txtAD, imgW, imgAS, imgAD, p_Sx, p_Si);
    k_mkWt4<<<dim3((320*KP+255)/256, 4), 256>>>(txtW, imgW, p_wtx, p_wti);
    k_csr2 <<<NB+1, 256>>>(ei_t, ei_i, p_offt, p_eidt, p_offi, p_eidi);

    // ---- layer 0 pipeline (txt + img + a1 side-branch merged) ----
    k_ms0   <<<MS_T + MS_I + MS_T, 256>>>(t2, v2, p_Sx, p_Si, w1, b1, kpm,
                                          p_asrc, p_adst, p_asrci, p_adsti, p_sbuf);
    k_malpha<<<AL_T + AL_I + NB, 256>>>(p_offt, p_eidt, ei_t, p_asrc, p_adst, p_al,
                                        p_offi, p_eidi, ei_i, p_asrci, p_adsti, p_ali,
                                        p_sbuf, p_prob);
    k_mxagg <<<XG_T + XG_I + NB*16, 320>>>(t2, p_al, p_offt, p_eidt, ei_t, p_ah,
                                           v2, p_ali, p_offi, p_eidi, ei_i, p_ahi,
                                           t2, score, p_prob, p_part, p_partc);
    k_mgemm <<<dim3(2, (NB*LT)/128 + (NB*KK)/128), 512, GSMEM>>>(p_ah, p_wtx, p_C,
                                                                  p_ahi, p_wti, p_Ci);
    k_mpost <<<XG_T + XG_I + 2*NB, 128>>>(p_C, txtB, gnn, lng, lnb, p_y, (long)LT*DD,
                                          p_Ci, imgB, p_v3a,
                                          p_Sx + 10*DD, p_asrc, p_adst,
                                          p_Si + 10*DD, p_asrci, p_adsti,
                                          p_part, p_partc, v2, out, p_x);

    // ---- layer 1 pipeline ----
    k_malpha<<<AL_T + AL_I, 256>>>(p_offt, p_eidt, ei_t, p_asrc, p_adst, p_al,
                                   p_offi, p_eidi, ei_i, p_asrci, p_adsti, p_ali,
                                   p_sbuf, p_prob);
    k_mxagg <<<XG_T + XG_I, 320>>>(p_y, p_al, p_offt, p_eidt, ei_t, p_ah,
                                   p_v3a, p_ali, p_offi, p_eidi, ei_i, p_ahi,
                                   t2, score, p_prob, p_part, p_partc);
    k_mgemm <<<dim3(2, (NB*LT)/128 + (NB*KK)/128), 512, GSMEM>>>(p_ah, p_wtx + WTSZ, p_C,
                                                                  p_ahi, p_wti + WTSZ, p_Ci);
    k_mpost <<<XG_T + XG_I, 128>>>(p_C, txtB + DD, gnn, lng, lnb, p_x, (long)(LT+1)*DD,
                                   p_Ci, imgB + DD, p_v3b,
                                   nullptr, nullptr, nullptr,
                                   nullptr, nullptr, nullptr,
                                   p_part, p_partc, v2, out, p_x);

    // ---- a2 branch ----
    k_logits <<<(NB*(LT+1)+7)/8, 256>>>(p_x, NB*(LT+1), w2, b2, npm, p_sbuf);
    k_softmax<<<NB, 256>>>(p_sbuf, LT+1, p_prob);
    k_wsum_part<<<dim3(NB,16), 320>>>(p_x, LT+1, p_prob, p_part);
    k_dotred<<<NB, 128>>>(p_part, p_v3b, out, 64);
}

// round 17
// speedup vs baseline: 1.0943x; 1.0943x over previous
#include <cuda_runtime.h>
#include <cuda_fp16.h>
#include <math.h>
#include <stdint.h>

// ---------------- problem constants ----------------
#define NB   64
#define LT   1024
#define KK   64
#define DD   300
#define HH   5
#define ET   2048
#define EI   512

#define KP   1536
#define NP   320
#define BK   32
#define NCHUNK (KP/BK)
#define WTSZ ((size_t)2*320*KP)

// ---------------- scratch ----------------
__device__ __half g_ah  [(size_t)NB*LT*KP];
__device__ float  g_C   [(size_t)NB*LT*NP];
__device__ __half g_wtx [2*WTSZ];
__device__ __half g_wti [2*WTSZ];
__device__ float  g_Sx  [2*10*DD];
__device__ float  g_Si  [2*10*DD];
__device__ float  g_y   [(size_t)NB*LT*DD];
__device__ float  g_x   [(size_t)NB*(LT+1)*DD];
__device__ float  g_v3a [(size_t)NB*KK*DD];
__device__ float  g_v3b [(size_t)NB*KK*DD];
__device__ float  g_asrc[NB*LT*HH];
__device__ float  g_adst[NB*LT*HH];
__device__ float  g_al_ [NB*ET*HH];
__device__ int    g_offt[NB*(LT+1)];
__device__ int    g_eidt[NB*ET];
__device__ int    g_offi[KK+1];
__device__ int    g_eidi[EI];
__device__ float  g_sbuf[NB*(LT+1)];
__device__ float  g_prob[NB*(LT+1)];
__device__ float  g_part[NB*16*DD];
__device__ float  g_partc[NB*16*DD];

__device__ __forceinline__ float wredsum(float v){
    #pragma unroll
    for (int o=16;o;o>>=1) v += __shfl_down_sync(0xffffffffu, v, o);
    return v;
}
__device__ __forceinline__ void mma_f16(float* c, uint32_t a0,uint32_t a1,uint32_t a2,uint32_t a3,
                                        uint32_t b0, uint32_t b1){
    asm volatile("mma.sync.aligned.m16n8k16.row.col.f32.f16.f16.f32 "
                 "{%0,%1,%2,%3},{%4,%5,%6,%7},{%8,%9},{%0,%1,%2,%3};"
                 : "+f"(c[0]),"+f"(c[1]),"+f"(c[2]),"+f"(c[3])
                 : "r"(a0),"r"(a1),"r"(a2),"r"(a3),"r"(b0),"r"(b1));
}
__device__ __forceinline__ void ldmx4(uint32_t addr, uint32_t* r){
    asm volatile("ldmatrix.sync.aligned.m8n8.x4.shared.b16 {%0,%1,%2,%3}, [%4];"
                 : "=r"(r[0]),"=r"(r[1]),"=r"(r[2]),"=r"(r[3]) : "r"(addr));
}
__device__ __forceinline__ void ldmx2(uint32_t addr, uint32_t* r){
    asm volatile("ldmatrix.sync.aligned.m8n8.x2.shared.b16 {%0,%1}, [%2];"
                 : "=r"(r[0]),"=r"(r[1]) : "r"(addr));
}
#define CP16(sm, gp) asm volatile("cp.async.cg.shared.global [%0], [%1], 16;" :: "r"(sm), "l"(gp))
#define CP_COMMIT()  asm volatile("cp.async.commit_group;")

// ---------------- CSR build ----------------
__global__ void k_csr(const int* __restrict__ EIp, long eiStride, int nodes, int E,
                      int* __restrict__ off, int* __restrict__ eid, int perBatch)
{
    int n = blockIdx.x;
    __shared__ int cnt[LT+1];
    __shared__ int cur[LT];
    for (int i=threadIdx.x; i<=nodes; i+=blockDim.x) cnt[i]=0;
    __syncthreads();
    const int* dstp = EIp + (size_t)eiStride*n + E;
    for (int j=threadIdx.x; j<E; j+=blockDim.x) atomicAdd(&cnt[dstp[j]+1], 1);
    __syncthreads();
    if (threadIdx.x==0){
        int run=0;
        for (int i=0;i<=nodes;i++){ run += cnt[i]; cnt[i]=run; }
    }
    __syncthreads();
    int* offg = off + (perBatch ? n*(nodes+1) : 0);
    for (int i=threadIdx.x; i<=nodes; i+=blockDim.x) offg[i]=cnt[i];
    for (int i=threadIdx.x; i<nodes;  i+=blockDim.x) cur[i]=cnt[i];
    __syncthreads();
    int* eidg = eid + (perBatch ? n*E : 0);
    for (int j=threadIdx.x; j<E; j+=blockDim.x){
        int d = dstp[j];
        int pos = atomicAdd(&cur[d], 1);
        eidg[pos] = j;
    }
}

// ---------------- batched S = W @ att ----------------
__global__ void k_mkS4(const float* __restrict__ txtW, const float* __restrict__ txtAS,
                       const float* __restrict__ txtAD,
                       const float* __restrict__ imgW, const float* __restrict__ imgAS,
                       const float* __restrict__ imgAD,
                       float* __restrict__ Sx, float* __restrict__ Si)
{
    int slot = blockIdx.y;
    int layer = slot & 1, isImg = slot >> 1;
    const float* W   = (isImg ? imgW  : txtW)  + (size_t)layer*DD*HH*DD;
    const float* aS  = (isImg ? imgAS : txtAS) + layer*HH*DD;
    const float* aD  = (isImg ? imgAD : txtAD) + layer*HH*DD;
    float* S         = (isImg ? Si    : Sx)    + layer*10*DD;

    int warp = threadIdx.x>>5, lane = threadIdx.x&31;
    int q = blockIdx.x*8 + warp;
    if (q >= 10*DD) return;
    int j = q/DD, d = q%DD;
    int h = j%HH;
    const float* att = (j<HH ? aS : aD) + h*DD;
    const float* wrow = W + ((size_t)d*HH + h)*DD;
    float acc=0.f;
    for (int dd=lane; dd<DD; dd+=32) acc += wrow[dd]*att[dd];
    acc = wredsum(acc);
    if (lane==0) S[q] = acc;
}

// ---------------- batched WT prep ----------------
__global__ void k_mkWt4(const float* __restrict__ txtW, const float* __restrict__ imgW,
                        __half* __restrict__ wtx, __half* __restrict__ wti)
{
    int slot = blockIdx.y;
    int layer = slot & 1, isImg = slot >> 1;
    const float* W = (isImg ? imgW : txtW) + (size_t)layer*DD*HH*DD;
    __half* wt     = (isImg ? wti  : wtx)  + (size_t)layer*WTSZ;

    int idx = blockIdx.x*blockDim.x + threadIdx.x;
    if (idx >= 320*KP) return;
    int n = idx / KP, k = idx % KP;
    float v = 0.f;
    if (n < DD && k < HH*DD){
        int h = k/DD, d = k%DD;
        v = W[((size_t)d*HH + h)*DD + n] * 0.2f;
    }
    __half hi = __float2half_rn(v);
    float lo = v - __half2float(hi);
    wt[idx] = hi;
    wt[(size_t)320*KP + idx] = __float2half_rn(lo);
}

// ---------------- scores: 4 rows/warp, S loaded once per lane-elem ----------------
__global__ void k_scores4(const float* __restrict__ X, const float* __restrict__ S,
                          int rows, float* __restrict__ asrc, float* __restrict__ adst)
{
    int warp = threadIdx.x>>5, lane = threadIdx.x&31;
    int row0 = (blockIdx.x*8 + warp)*4;
    if (row0 >= rows) return;
    const float* xr = X + (size_t)row0*DD;
    float acc[4][10];
    #pragma unroll
    for (int r=0;r<4;r++)
        #pragma unroll
        for (int j=0;j<10;j++) acc[r][j]=0.f;
    for (int d=lane; d<DD; d+=32){
        float s[10];
        #pragma unroll
        for (int j=0;j<10;j++) s[j] = S[j*DD+d];
        #pragma unroll
        for (int r=0;r<4;r++){
            float xv = xr[(size_t)r*DD + d];
            #pragma unroll
            for (int j=0;j<10;j++) acc[r][j] += xv * s[j];
        }
    }
    #pragma unroll
    for (int r=0;r<4;r++){
        #pragma unroll
        for (int j=0;j<10;j++) acc[r][j] = wredsum(acc[r][j]);
        if (lane==0){
            int row = row0 + r;
            #pragma unroll
            for (int h=0;h<HH;h++){ asrc[row*HH+h]=acc[r][h]; adst[row*HH+h]=acc[r][HH+h]; }
        }
    }
}

// ---------------- logits: 4 rows/warp ----------------
__global__ void k_logits4(const float* __restrict__ X, int rows,
                          const float* __restrict__ w, const float* __restrict__ b,
                          const int* __restrict__ mask, float* __restrict__ s)
{
    int warp = threadIdx.x>>5, lane = threadIdx.x&31;
    int row0 = (blockIdx.x*8 + warp)*4;
    if (row0 >= rows) return;
    const float* xr = X + (size_t)row0*DD;
    float acc[4] = {0,0,0,0};
    int nvalid = min(4, rows - row0);
    for (int d=lane; d<DD; d+=32){
        float wv = w[d];
        #pragma unroll
        for (int r=0;r<4;r++)
            if (r < nvalid) acc[r] += xr[(size_t)r*DD + d] * wv;
    }
    #pragma unroll
    for (int r=0;r<4;r++){
        acc[r] = wredsum(acc[r]);
        if (lane==0 && r < nvalid){
            int row = row0 + r;
            s[row] = mask[row] ? -1e30f : acc[r] + b[0];
        }
    }
}

// ---------------- fused edge + alpha softmax ----------------
__global__ void k_alpha2(const int* __restrict__ off, const int* __restrict__ eid, int perBatch,
                         const int* __restrict__ EIp, long eiStride,
                         const float* __restrict__ asrc, const float* __restrict__ adst,
                         float* __restrict__ alpha, int nodes, int E, int total)
{
    int idx = blockIdx.x*blockDim.x + threadIdx.x;
    if (idx >= total) return;
    int h = idx % HH;
    int node = (idx/HH) % nodes;
    int n = idx/(HH*nodes);
    const int* o  = off + (perBatch ? n*(nodes+1) : 0);
    const int* ee = eid + (perBatch ? n*E : 0);
    int s=o[node], t=o[node+1];
    if (s==t) return;
    const int* srcp = EIp + (size_t)eiStride*n;
    const float* as_ = asrc + (size_t)n*nodes*HH;
    float ad = adst[((size_t)n*nodes+node)*HH + h];
    float m=-1e30f;
    for (int q=s;q<t;q++){
        float e = as_[srcp[ee[q]]*HH + h] + ad;
        e = e > 0.f ? e : 0.2f*e;
        m = fmaxf(m, e);
    }
    float den=0.f;
    for (int q=s;q<t;q++){
        float e = as_[srcp[ee[q]]*HH + h] + ad;
        e = e > 0.f ? e : 0.2f*e;
        den += expf(e-m);
    }
    float inv = 1.f/(den + 1e-16f);
    for (int q=s;q<t;q++){
        int j = ee[q];
        float e = as_[srcp[j]*HH + h] + ad;
        e = e > 0.f ? e : 0.2f*e;
        alpha[((size_t)n*E + j)*HH + h] = expf(e-m)*inv;
    }
}

// ---------------- xagg ----------------
__global__ void k_xagg(const float* __restrict__ X, const float* __restrict__ alpha,
                       const int* __restrict__ off, const int* __restrict__ eid, int perBatch,
                       const int* __restrict__ EIp, long eiStride, int nodes, int E,
                       __half* __restrict__ outA)
{
    int node = blockIdx.x, n = blockIdx.y;
    int tid = threadIdx.x;  // 128
    const int* o  = off + (perBatch ? n*(nodes+1) : 0);
    const int* ee = eid + (perBatch ? n*E : 0);
    int s=o[node], t=o[node+1];
    const int* srcp = EIp + (size_t)eiStride*n;
    const float* Xb = X + (size_t)n*nodes*DD;
    const float* al0 = alpha + (size_t)n*E*HH;

    int d0 = tid, d1 = tid+128, d2 = tid+256;
    bool v2 = (d2 < DD);

    float acc[HH][3];
    #pragma unroll
    for (int h=0;h<HH;h++){ acc[h][0]=0.f; acc[h][1]=0.f; acc[h][2]=0.f; }

    for (int q=s; q<t; q++){
        int j = ee[q];
        int src = srcp[j];
        const float* xr = Xb + (size_t)src*DD;
        float x0 = xr[d0];
        float x1 = xr[d1];
        float x2 = v2 ? xr[d2] : 0.f;
        const float* ap = al0 + (size_t)j*HH;
        #pragma unroll
        for (int h=0;h<HH;h++){
            float a = ap[h];
            acc[h][0] += a*x0;
            acc[h][1] += a*x1;
            acc[h][2] += a*x2;
        }
    }

    __half* oh = outA + (size_t)(n*nodes+node)*KP;
    #pragma unroll
    for (int h=0;h<HH;h++){
        int c0 = h*DD + d0, c1 = h*DD + d1, c2 = h*DD + d2;
        oh[c0] = __float2half_rn(acc[h][0]);
        oh[c1] = __float2half_rn(acc[h][1]);
        if (v2) oh[c2] = __float2half_rn(acc[h][2]);
    }
    if (tid < KP - HH*DD)
        oh[HH*DD + tid] = __float2half_rn(0.f);
}

// ---------------- 2-term split-fp16 GEMM, BM=128, 3-stage cp.async ----------------
#define APL 10240
#define BPL 12800
#define STG (APL + 2*BPL)
#define GSMEM (3*STG)
__global__ void __launch_bounds__(512,1)
k_gemm_f16(const __half* __restrict__ Ain, const __half* __restrict__ wt,
           float* __restrict__ C, int M)
{
    extern __shared__ char smem[];
    uint32_t sm_u = (uint32_t)__cvta_generic_to_shared(smem);

    int tid = threadIdx.x;
    int bm = blockIdx.y*128, bn = blockIdx.x*160;
    int warp = tid>>5, lane = tid&31;
    int wm = warp>>2, wn = warp&3;
    int g = lane>>2, tig = lane&3;

    float acc[2][5][4];
    #pragma unroll
    for (int t=0;t<2;t++)
        #pragma unroll
        for (int j=0;j<5;j++)
            #pragma unroll
            for (int r=0;r<4;r++) acc[t][j][r]=0.f;

    uint32_t a_frag  = (uint32_t)((wm*32 + (lane&7) + ((lane>>3)&1)*8)*80 + ((lane>>4)&1)*16);
    uint32_t b_frag  = (uint32_t)(((lane&7) + ((lane>>4)&1)*8)*80 + ((lane>>3)&1)*16);
    uint32_t b_frag2 = (uint32_t)(((wn*40+32) + (lane&7))*80 + ((lane>>3)&1)*16);

    int ar = tid>>2, as_ = tid&3;
    const __half* gAh = Ain + (size_t)(bm+ar)*KP + as_*8;
    uint32_t aoff = (uint32_t)(ar*80 + as_*16);
    const __half* WTh = wt;
    const __half* WTl = wt + (size_t)320*KP;
    int b0n = tid>>2,       b0s = tid&3;
    int b1n = (tid+512)>>2, b1s = tid&3;
    bool bv = (tid < 128);
    const __half* gB0h = WTh + (size_t)(bn+b0n)*KP + b0s*8;
    const __half* gB0l = WTl + (size_t)(bn+b0n)*KP + b0s*8;
    const __half* gB1h = WTh + (size_t)(bn+b1n)*KP + b1s*8;
    const __half* gB1l = WTl + (size_t)(bn+b1n)*KP + b1s*8;
    uint32_t bo0 = (uint32_t)(b0n*80 + b0s*16);
    uint32_t bo1 = (uint32_t)(b1n*80 + b1s*16);

    #define COPY_CHUNK(kc, s) do { \
        int _k = (kc)*BK; \
        uint32_t _b = sm_u + (s)*STG; \
        CP16(_b + aoff, gAh + _k); \
        CP16(_b + APL + bo0, gB0h + _k); \
        CP16(_b + APL + BPL + bo0, gB0l + _k); \
        if (bv){ \
            CP16(_b + APL + bo1, gB1h + _k); \
            CP16(_b + APL + BPL + bo1, gB1l + _k); \
        } \
        CP_COMMIT(); \
    } while(0)

    COPY_CHUNK(0, 0);
    COPY_CHUNK(1, 1);
    int s = 0;
    for (int kc=0; kc<NCHUNK; kc++){
        if (kc+2 < NCHUNK){
            COPY_CHUNK(kc+2, (kc+2)%3);
            asm volatile("cp.async.wait_group 2;");
        } else if (kc+1 < NCHUNK){
            asm volatile("cp.async.wait_group 1;");
        } else {
            asm volatile("cp.async.wait_group 0;");
        }
        __syncthreads();
        uint32_t Ab = sm_u + s*STG;
        uint32_t Bh = Ab + APL;
        uint32_t Bl = Bh + BPL;
        #pragma unroll
        for (int ks=0; ks<2; ks++){
            uint32_t kbyte = ks*32;
            uint32_t ahf[2][4];
            #pragma unroll
            for (int t=0;t<2;t++)
                ldmx4(Ab + t*(16*80) + kbyte + a_frag, ahf[t]);
            uint32_t bh[5][2], bl[5][2];
            #pragma unroll
            for (int jj=0;jj<2;jj++){
                uint32_t r4[4];
                uint32_t base = (uint32_t)((wn*40 + jj*16)*80) + kbyte + b_frag;
                ldmx4(Bh + base, r4);
                bh[jj*2+0][0]=r4[0]; bh[jj*2+0][1]=r4[1];
                bh[jj*2+1][0]=r4[2]; bh[jj*2+1][1]=r4[3];
                ldmx4(Bl + base, r4);
                bl[jj*2+0][0]=r4[0]; bl[jj*2+0][1]=r4[1];
                bl[jj*2+1][0]=r4[2]; bl[jj*2+1][1]=r4[3];
            }
            {
                uint32_t r2[2];
                ldmx2(Bh + kbyte + b_frag2, r2);
                bh[4][0]=r2[0]; bh[4][1]=r2[1];
                ldmx2(Bl + kbyte + b_frag2, r2);
                bl[4][0]=r2[0]; bl[4][1]=r2[1];
            }
            #pragma unroll
            for (int j=0;j<5;j++){
                #pragma unroll
                for (int t=0;t<2;t++){
                    mma_f16(acc[t][j], ahf[t][0],ahf[t][1],ahf[t][2],ahf[t][3], bh[j][0],bh[j][1]);
                    mma_f16(acc[t][j], ahf[t][0],ahf[t][1],ahf[t][2],ahf[t][3], bl[j][0],bl[j][1]);
                }
            }
        }
        __syncthreads();
        s = (s+1)%3;
    }

    #pragma unroll
    for (int t=0;t<2;t++){
        int row0 = bm + wm*32 + t*16 + g;
        #pragma unroll
        for (int j=0;j<5;j++){
            int n0 = bn + wn*40 + j*8 + 2*tig;
            *(float2*)&C[(size_t)row0*NP + n0]     = make_float2(acc[t][j][0], acc[t][j][1]);
            *(float2*)&C[(size_t)(row0+8)*NP + n0] = make_float2(acc[t][j][2], acc[t][j][3]);
        }
    }
}

// ---------------- post: bias+mask+relu+LN, optional fused next-layer scores ----------------
__global__ void k_post(const float* __restrict__ C, const float* __restrict__ bias,
                       const int* __restrict__ gnnMask,
                       const float* __restrict__ lng, const float* __restrict__ lnb,
                       float* __restrict__ out, long outBatchStride, int nodes,
                       const float* __restrict__ Snext,
                       float* __restrict__ asrc, float* __restrict__ adst)
{
    int node = blockIdx.x, n = blockIdx.y;
    int tid = threadIdx.x;   // 128
    size_t row = (size_t)n*nodes + node;
    const float* cr = C + row*NP;
    int d0=tid, d1=tid+128, d2=tid+256;
    bool v2 = (d2 < DD);
    bool msk = (gnnMask != nullptr) && (gnnMask[n] != 0);
    float g0 = msk ? 0.f : cr[d0] + bias[d0];
    float g1 = msk ? 0.f : cr[d1] + bias[d1];
    float g2 = v2 ? (msk ? 0.f : cr[d2] + bias[d2]) : 0.f;
    float r0 = fmaxf(g0,0.f), r1 = fmaxf(g1,0.f), r2 = fmaxf(g2,0.f);

    __shared__ float sS[4], sQ[4];
    int warp = tid>>5, lane = tid&31;
    float lsum = r0 + r1 + r2;
    float lsq  = r0*r0 + r1*r1 + r2*r2;
    lsum = wredsum(lsum); lsq = wredsum(lsq);
    if (lane==0){ sS[warp]=lsum; sQ[warp]=lsq; }
    __syncthreads();
    if (tid==0){
        float S=0.f, Q=0.f;
        for (int w=0;w<4;w++){ S+=sS[w]; Q+=sQ[w]; }
        sS[0]=S; sQ[0]=Q;
    }
    __syncthreads();
    float mu  = sS[0]*(1.f/300.f);
    float var = sQ[0]*(1.f/300.f) - mu*mu;
    float rstd = rsqrtf(var + 1e-5f);
    float o0 = (r0-mu)*rstd*lng[d0] + lnb[d0];
    float o1 = (r1-mu)*rstd*lng[d1] + lnb[d1];
    float o2 = v2 ? ((r2-mu)*rstd*lng[d2] + lnb[d2]) : 0.f;
    float* orow = out + (size_t)n*outBatchStride + (size_t)node*DD;
    orow[d0] = o0;
    orow[d1] = o1;
    if (v2) orow[d2] = o2;

    if (Snext){
        __shared__ float sJ[4][10];
        #pragma unroll
        for (int j=0;j<10;j++){
            const float* sv = Snext + j*DD;
            float p = o0*sv[d0] + o1*sv[d1] + (v2 ? o2*sv[d2] : 0.f);
            p = wredsum(p);
            if (lane==0) sJ[warp][j] = p;
        }
        __syncthreads();
        if (tid < 10){
            float v = sJ[0][tid] + sJ[1][tid] + sJ[2][tid] + sJ[3][tid];
            if (tid < HH) asrc[row*HH + tid] = v;
            else          adst[row*HH + (tid-HH)] = v;
        }
    }
}

// ---------------- softmax ----------------
__global__ void k_softmax(const float* __restrict__ s, int Lrow, float* __restrict__ p)
{
    int n = blockIdx.x;
    int tid = threadIdx.x, warp=tid>>5, lane=tid&31;
    __shared__ float red[32];
    const float* sb = s + (size_t)n*Lrow;
    float m=-1e30f;
    for (int l=tid; l<Lrow; l+=1024) m = fmaxf(m, sb[l]);
    #pragma unroll
    for (int o=16;o;o>>=1) m = fmaxf(m, __shfl_down_sync(0xffffffffu, m, o));
    if (lane==0) red[warp]=m;
    __syncthreads();
    if (tid==0){ float v=red[0]; for(int i=1;i<32;i++) v=fmaxf(v,red[i]); red[0]=v; }
    __syncthreads();
    m = red[0];
    __syncthreads();
    float sum=0.f;
    for (int l=tid; l<Lrow; l+=1024) sum += expf(sb[l]-m);
    sum = wredsum(sum);
    if (lane==0) red[warp]=sum;
    __syncthreads();
    if (tid==0){ float v=0.f; for(int i=0;i<32;i++) v+=red[i]; red[0]=v; }
    __syncthreads();
    float inv = 1.f/red[0];
    for (int l=tid; l<Lrow; l+=1024) p[(size_t)n*Lrow + l] = expf(sb[l]-m)*inv;
}

// ---------------- fused a1 weighted-sum + c partials ----------------
__global__ void k_wsumc_part(const float* __restrict__ t2, const float* __restrict__ score,
                             const float* __restrict__ p,
                             float* __restrict__ partW, float* __restrict__ partC)
{
    int n = blockIdx.x, cid = blockIdx.y;
    int d = threadIdx.x;
    if (d >= DD) return;
    int chunk = LT/16;
    int l0 = cid*chunk, l1 = l0+chunk;
    const float* Tb = t2    + (size_t)n*LT*DD;
    const float* Sb = score + (size_t)n*LT*DD;
    const float* pb = p + (size_t)n*LT;
    float aw=0.f, ac=0.f;
    for (int l=l0; l<l1; l++){
        float tv = Tb[(size_t)l*DD+d];
        aw += pb[l]*tv;
        ac += Sb[(size_t)l*DD+d]*tv;
    }
    partW[((size_t)n*16+cid)*DD + d] = aw;
    partC[((size_t)n*16+cid)*DD + d] = ac;
}

// ---------------- a2 weighted-sum partials ----------------
__global__ void k_wsum_part(const float* __restrict__ X, int Lrow,
                            const float* __restrict__ p, float* __restrict__ part)
{
    int n = blockIdx.x, cid = blockIdx.y;
    int d = threadIdx.x;
    if (d >= DD) return;
    int chunk = (Lrow+15)/16;
    int l0 = cid*chunk, l1 = min(Lrow, l0+chunk);
    const float* Xb = X + ((size_t)n*Lrow)*DD;
    const float* pb = p + (size_t)n*Lrow;
    float acc=0.f;
    for (int l=l0; l<l1; l++) acc += pb[l]*Xb[(size_t)l*DD+d];
    part[((size_t)n*16+cid)*DD + d] = acc;
}

// ---------------- c reduce ----------------
__global__ void k_c_red(const float* __restrict__ part, float* __restrict__ xbuf)
{
    int n = blockIdx.x; int d = threadIdx.x;
    if (d >= DD) return;
    float acc=0.f;
    for (int c=0;c<16;c++) acc += part[((size_t)n*16+c)*DD + d];
    xbuf[((size_t)n*(LT+1) + LT)*DD + d] = acc;
}

// ---------------- fused part-reduce + dot ----------------
__global__ void k_dotred(const float* __restrict__ part, const float* __restrict__ V,
                         float* __restrict__ out, int colOff)
{
    int n = blockIdx.x;
    int tid = threadIdx.x;            // 512
    __shared__ float tb[DD];
    if (tid < DD){
        float acc=0.f;
        #pragma unroll
        for (int c=0;c<16;c++) acc += part[((size_t)n*16+c)*DD + tid];
        tb[tid] = acc;
    }
    __syncthreads();
    int warp = tid>>5, lane = tid&31;
    for (int k=warp; k<KK; k+=16){
        const float* v = V + ((size_t)n*KK + k)*DD;
        float acc=0.f;
        for (int d=lane; d<DD; d+=32) acc += tb[d]*v[d];
        acc = wredsum(acc);
        if (lane==0) out[n*128 + colOff + k] = acc * 0.05773502691896258f;
    }
}

// ---------------- launch ----------------
extern "C" void kernel_launch(void* const* d_in, const int* in_sizes, int n_in,
                              void* d_out, int out_size)
{
    const float* t2    = (const float*)d_in[0];
    const float* v2    = (const float*)d_in[1];
    const float* score = (const float*)d_in[2];
    const int*   ei_t  = (const int*)  d_in[3];
    const int*   gnn   = (const int*)  d_in[4];
    const int*   kpm   = (const int*)  d_in[5];
    const int*   npm   = (const int*)  d_in[6];
    const int*   ei_i  = (const int*)  d_in[7];
    const float* txtW  = (const float*)d_in[8];
    const float* txtAS = (const float*)d_in[9];
    const float* txtAD = (const float*)d_in[10];
    const float* txtB  = (const float*)d_in[11];
    const float* imgW  = (const float*)d_in[12];
    const float* imgAS = (const float*)d_in[13];
    const float* imgAD = (const float*)d_in[14];
    const float* imgB  = (const float*)d_in[15];
    const float* w1    = (const float*)d_in[16];
    const float* b1    = (const float*)d_in[17];
    const float* w2    = (const float*)d_in[18];
    const float* b2    = (const float*)d_in[19];
    const float* lng   = (const float*)d_in[20];
    const float* lnb   = (const float*)d_in[21];
    float* out = (float*)d_out;

    __half *p_ah,*p_wtx,*p_wti;
    float *p_C,*p_Sx,*p_Si,*p_y,*p_x,*p_v3a,*p_v3b;
    float *p_asrc,*p_adst,*p_al,*p_sbuf,*p_prob,*p_part,*p_partc;
    int *p_offt,*p_eidt,*p_offi,*p_eidi;
    cudaGetSymbolAddress((void**)&p_ah, g_ah);
    cudaGetSymbolAddress((void**)&p_C, g_C);
    cudaGetSymbolAddress((void**)&p_wtx, g_wtx);
    cudaGetSymbolAddress((void**)&p_wti, g_wti);
    cudaGetSymbolAddress((void**)&p_Sx, g_Sx);
    cudaGetSymbolAddress((void**)&p_Si, g_Si);
    cudaGetSymbolAddress((void**)&p_y, g_y);
    cudaGetSymbolAddress((void**)&p_x, g_x);
    cudaGetSymbolAddress((void**)&p_v3a, g_v3a);
    cudaGetSymbolAddress((void**)&p_v3b, g_v3b);
    cudaGetSymbolAddress((void**)&p_asrc, g_asrc);
    cudaGetSymbolAddress((void**)&p_adst, g_adst);
    cudaGetSymbolAddress((void**)&p_al, g_al_);
    cudaGetSymbolAddress((void**)&p_sbuf, g_sbuf);
    cudaGetSymbolAddress((void**)&p_prob, g_prob);
    cudaGetSymbolAddress((void**)&p_part, g_part);
    cudaGetSymbolAddress((void**)&p_partc, g_partc);
    cudaGetSymbolAddress((void**)&p_offt, g_offt);
    cudaGetSymbolAddress((void**)&p_eidt, g_eidt);
    cudaGetSymbolAddress((void**)&p_offi, g_offi);
    cudaGetSymbolAddress((void**)&p_eidi, g_eidi);

    static bool inited = false;
    if (!inited){
        cudaFuncSetAttribute(k_gemm_f16, cudaFuncAttributeMaxDynamicSharedMemorySize, GSMEM);
        inited = true;
    }

    // batched weight prep
    k_mkS4 <<<dim3((10*DD+7)/8, 4), 256>>>(txtW, txtAS, txtAD, imgW, imgAS, imgAD, p_Sx, p_Si);
    k_mkWt4<<<dim3((320*KP+255)/256, 4), 256>>>(txtW, imgW, p_wtx, p_wti);

    // CSR builds
    k_csr<<<NB, 256>>>(ei_t, 2L*ET, LT, ET, p_offt, p_eidt, 1);
    k_csr<<<1,  256>>>(ei_i, 0L,    KK, EI, p_offi, p_eidi, 0);

    // a1 branch + c row
    k_logits4<<<(NB*LT/4+7)/8, 256>>>(t2, NB*LT, w1, b1, kpm, p_sbuf);
    k_softmax<<<NB, 1024>>>(p_sbuf, LT, p_prob);
    k_wsumc_part<<<dim3(NB,16), 320>>>(t2, score, p_prob, p_part, p_partc);
    k_dotred<<<NB, 512>>>(p_part, v2, out, 0);
    k_c_red <<<NB, 320>>>(p_partc, p_x);

    // ---- txt GAT layer 0 ----
    k_scores4<<<(NB*LT/4+7)/8, 256>>>(t2, p_Sx, NB*LT, p_asrc, p_adst);
    k_alpha2 <<<(NB*LT*HH+255)/256, 256>>>(p_offt, p_eidt, 1, ei_t, 2L*ET,
                                           p_asrc, p_adst, p_al, LT, ET, NB*LT*HH);
    k_xagg   <<<dim3(LT,NB), 128>>>(t2, p_al, p_offt, p_eidt, 1, ei_t, 2L*ET, LT, ET, p_ah);
    k_gemm_f16<<<dim3(2, NB*LT/128), 512, GSMEM>>>(p_ah, p_wtx, p_C, NB*LT);
    k_post<<<dim3(LT,NB), 128>>>(p_C, txtB, gnn, lng, lnb, p_y, (long)LT*DD, LT,
                                 p_Sx + 10*DD, p_asrc, p_adst);

    // ---- txt GAT layer 1 ----
    k_alpha2 <<<(NB*LT*HH+255)/256, 256>>>(p_offt, p_eidt, 1, ei_t, 2L*ET,
                                           p_asrc, p_adst, p_al, LT, ET, NB*LT*HH);
    k_xagg   <<<dim3(LT,NB), 128>>>(p_y, p_al, p_offt, p_eidt, 1, ei_t, 2L*ET, LT, ET, p_ah);
    k_gemm_f16<<<dim3(2, NB*LT/128), 512, GSMEM>>>(p_ah, p_wtx + WTSZ, p_C, NB*LT);
    k_post<<<dim3(LT,NB), 128>>>(p_C, txtB + DD, gnn, lng, lnb, p_x, (long)(LT+1)*DD, LT,
                                 nullptr, nullptr, nullptr);

    // ---- img GAT layer 0 ----
    k_scores4<<<(NB*KK/4+7)/8, 256>>>(v2, p_Si, NB*KK, p_asrc, p_adst);
    k_alpha2 <<<(NB*KK*HH+255)/256, 256>>>(p_offi, p_eidi, 0, ei_i, 0L,
                                           p_asrc, p_adst, p_al, KK, EI, NB*KK*HH);
    k_xagg   <<<dim3(KK,NB), 128>>>(v2, p_al, p_offi, p_eidi, 0, ei_i, 0L, KK, EI, p_ah);
    k_gemm_f16<<<dim3(2, NB*KK/128), 512, GSMEM>>>(p_ah, p_wti, p_C, NB*KK);
    k_post<<<dim3(KK,NB), 128>>>(p_C, imgB, nullptr, lng, lnb, p_v3a, (long)KK*DD, KK,
                                 p_Si + 10*DD, p_asrc, p_adst);

    // ---- img GAT layer 1 ----
    k_alpha2 <<<(NB*KK*HH+255)/256, 256>>>(p_offi, p_eidi, 0, ei_i, 0L,
                                           p_asrc, p_adst, p_al, KK, EI, NB*KK*HH);
    k_xagg   <<<dim3(KK,NB), 128>>>(p_v3a, p_al, p_offi, p_eidi, 0, ei_i, 0L, KK, EI, p_ah);
    k_gemm_f16<<<dim3(2, NB*KK/128), 512, GSMEM>>>(p_ah, p_wti + WTSZ, p_C, NB*KK);
    k_post<<<dim3(KK,NB), 128>>>(p_C, imgB + DD, nullptr, lng, lnb, p_v3b, (long)KK*DD, KK,
                                 nullptr, nullptr, nullptr);

    // a2 branch
    k_logits4<<<(NB*(LT+1)/4+7)/8 + 1, 256>>>(p_x, NB*(LT+1), w2, b2, npm, p_sbuf);
    k_softmax<<<NB, 1024>>>(p_sbuf, LT+1, p_prob);
    k_wsum_part<<<dim3(NB,16), 320>>>(p_x, LT+1, p_prob, p_part);
    k_dotred<<<NB, 512>>>(p_part, p_v3b, out, 64);
}